// round 15
// baseline (speedup 1.0000x reference)
#include <cuda_runtime.h>

// ---------------------------------------------------------------------------
// DiscriminativeClueCorrection — R14 config + float4/128-thread attn2.
// Output layout (float32): [loss(1)] [corrected(512*512)] [cluster_scores(512*3)]
// ---------------------------------------------------------------------------

constexpr int kB    = 512;
constexpr int kM    = 96;
constexpr int kD    = 512;
constexpr int kH    = 8;
constexpr int kDH   = 64;
constexpr int kNC   = 3;
constexpr int kNegC = 1024;
constexpr float kEps = 1e-8f;

// ----- device scratch --------------------------------------------------------
__device__ float g_vn   [kB * kD];
__device__ float g_qp   [4 * kB * kD];      // qproj split-K x4 partials
__device__ float g_qt   [kB * kH * kD];     // per-b transformed key weights (×1/8)
__device__ float g_attn [kB * kM * kH];     // softmaxed attention probs
__device__ float g_tctx [kB * kH * kD];
__device__ float g_ctxp [4 * kB * kD];      // ctx split-K x4 partials
__device__ float g_corr [2 * kB * kD];      // corr split-K x2 partials
__device__ float g_pos  [kB];
__device__ float g_negs [kNegC * kD];
__device__ float g_nsims[2 * kB * kNegC];   // nsims split-K x2 partials

__device__ __forceinline__ float warp_sum(float v) {
#pragma unroll
    for (int o = 16; o > 0; o >>= 1) v += __shfl_xor_sync(0xffffffffu, v, o);
    return v;
}
__device__ __forceinline__ float warp_max(float v) {
#pragma unroll
    for (int o = 16; o > 0; o >>= 1) v = fmaxf(v, __shfl_xor_sync(0xffffffffu, v, o));
    return v;
}

// ----- f32x2 packed helpers ---------------------------------------------------
__device__ __forceinline__ unsigned long long dup2(float v) {
    unsigned long long r;
    asm("mov.b64 %0, {%1,%1};" : "=l"(r) : "f"(v));
    return r;
}
__device__ __forceinline__ void fma2(unsigned long long& acc, unsigned long long a,
                                     unsigned long long b) {
    asm("fma.rn.f32x2 %0, %1, %2, %0;" : "+l"(acc) : "l"(a), "l"(b));
}
__device__ __forceinline__ float2 unpack2(unsigned long long v) {
    float2 f;
    asm("mov.b64 {%0,%1}, %2;" : "=f"(f.x), "=f"(f.y) : "l"(v));
    return f;
}

// ----- shared GEMM core: 64x64 tile, BK=16, dup-A FFMA2 (R4-proven) -----------
template <int NPART>
__device__ __forceinline__ void gemm_core(
    const float* __restrict__ A, size_t aPartStride,
    const float* __restrict__ abias, int lda,
    const float* __restrict__ Bm, int ldb,
    float* __restrict__ C, int ldc, int K,
    float (&As2)[16][128], float (&Bs)[16][64])
{
    int tid = threadIdx.x;
    int tx = tid & 15, ty = tid >> 4;
    int lr = tid >> 2, lk = (tid & 3) << 2;

    const float* Aload = A + (size_t)lr * lda + lk;
    const float* Bload = Bm + (size_t)lr * ldb + lk;

    auto loadA = [&](int k0) -> float4 {
        float4 r = *(const float4*)(Aload + k0);
#pragma unroll
        for (int p = 1; p < NPART; p++) {
            float4 tq = *(const float4*)(Aload + p * aPartStride + k0);
            r.x += tq.x; r.y += tq.y; r.z += tq.z; r.w += tq.w;
        }
        if (abias) {
            float4 tq = *(const float4*)(abias + k0 + lk);
            r.x += tq.x; r.y += tq.y; r.z += tq.z; r.w += tq.w;
        }
        return r;
    };

    float4 a4 = loadA(0);
    float4 b4 = *(const float4*)Bload;

    unsigned long long acc[4][2] = {};
    for (int k0 = 0; k0 < K; k0 += 16) {
        *(unsigned long long*)&As2[lk + 0][2 * lr] = dup2(a4.x);
        *(unsigned long long*)&As2[lk + 1][2 * lr] = dup2(a4.y);
        *(unsigned long long*)&As2[lk + 2][2 * lr] = dup2(a4.z);
        *(unsigned long long*)&As2[lk + 3][2 * lr] = dup2(a4.w);
        Bs[lk + 0][lr] = b4.x; Bs[lk + 1][lr] = b4.y;
        Bs[lk + 2][lr] = b4.z; Bs[lk + 3][lr] = b4.w;
        __syncthreads();
        if (k0 + 16 < K) {
            a4 = loadA(k0 + 16);
            b4 = *(const float4*)(Bload + k0 + 16);
        }
#pragma unroll
        for (int k = 0; k < 16; k++) {
            ulonglong2 ap0 = *(const ulonglong2*)&As2[k][ty * 8];
            ulonglong2 ap1 = *(const ulonglong2*)&As2[k][ty * 8 + 4];
            ulonglong2 bp  = *(const ulonglong2*)&Bs[k][tx * 4];
            fma2(acc[0][0], ap0.x, bp.x); fma2(acc[0][1], ap0.x, bp.y);
            fma2(acc[1][0], ap0.y, bp.x); fma2(acc[1][1], ap0.y, bp.y);
            fma2(acc[2][0], ap1.x, bp.x); fma2(acc[2][1], ap1.x, bp.y);
            fma2(acc[3][0], ap1.y, bp.x); fma2(acc[3][1], ap1.y, bp.y);
        }
        __syncthreads();
    }
#pragma unroll
    for (int i = 0; i < 4; i++) {
        float2 c0 = unpack2(acc[i][0]);
        float2 c1 = unpack2(acc[i][1]);
        *(float4*)&C[(size_t)(ty * 4 + i) * ldc + tx * 4]
            = make_float4(c0.x, c0.y, c1.x, c1.y);
    }
}

// ----- generic NT GEMM wrapper --------------------------------------------------
template <int NPART>
__global__ void __launch_bounds__(256)
k_gemm_nt(const float* __restrict__ A, size_t aPartStride,
          const float* __restrict__ abias, int lda, int sAz,
          const float* __restrict__ Bm, int ldb, int sBz,
          float* __restrict__ C, int ldc, int sCz, int K) {
    __shared__ __align__(16) float As2[16][128];
    __shared__ __align__(16) float Bs[16][64];
    size_t aoff = (size_t)blockIdx.z * sAz + (size_t)blockIdx.y * 64 * lda;
    const float* Ar  = A + aoff;
    const float* abr = abias ? abias + (size_t)blockIdx.z * sAz : nullptr;
    const float* Br  = Bm + (size_t)blockIdx.z * sBz + (size_t)blockIdx.x * 64 * ldb;
    float* Cr = C + (size_t)blockIdx.z * sCz + (size_t)blockIdx.y * 64 * ldc
                  + (size_t)blockIdx.x * 64;
    gemm_core<NPART>(Ar, aPartStride, abr, lda, Br, ldb, Cr, ldc, K, As2, Bs);
}

// ----- merged: qproj split-K x4 (blocks 0..255) + row norms (256..1279) --------
__global__ void __launch_bounds__(256)
k_pre_qproj(const float* __restrict__ vis, const float* __restrict__ tmem,
            const float* __restrict__ ipw, float* __restrict__ out_loss) {
    __shared__ __align__(16) float As2[16][128];
    __shared__ __align__(16) float Bs[16][64];
    __shared__ float red[8];
    if (blockIdx.x < 256) {
        int bx = blockIdx.x;
        int kc = bx >> 6, yt = (bx >> 3) & 7, xt = bx & 7;
        const float* A = vis + (size_t)yt * 64 * kD + kc * 128;
        const float* B = ipw + (size_t)xt * 64 * kD + kc * 128;
        float* C = g_qp + (size_t)kc * kB * kD + (size_t)yt * 64 * kD + xt * 64;
        gemm_core<1>(A, 0, nullptr, kD, B, kD, C, kD, 128, As2, Bs);
    } else {
        int idx = blockIdx.x - 256;           // 0..1023
        int t = threadIdx.x;
        if (blockIdx.x == 256 && t == 0) out_loss[0] = 0.f;   // init loss accumulator
        const float* x;
        float* outp;
        if (idx < kB) { x = vis + (size_t)idx * kD;  outp = g_vn + (size_t)idx * kD; }
        else          { x = tmem + (size_t)idx * kD; outp = g_negs + (size_t)idx * kD; }
        float ss = 0.f;
        for (int i = t; i < kD; i += 256) { float v = x[i]; ss += v * v; }
        ss = warp_sum(ss);
        if ((t & 31) == 0) red[t >> 5] = ss;
        __syncthreads();
        float tot = red[0] + red[1] + red[2] + red[3] + red[4] + red[5] + red[6] + red[7];
        float inv = 1.0f / fmaxf(sqrtf(tot), kEps);
        for (int i = t; i < kD; i += 256) outp[i] = x[i] * inv;
    }
}

// ----- qt[b,h,d] = (1/8) * sum_dh (Σ4 q partials + bq)[b,h,dh] * Wk[.,d] -------
__global__ void __launch_bounds__(256)
k_qt_kernel(const float* __restrict__ wk, const float* __restrict__ bq) {
    int h = blockIdx.z, b0 = blockIdx.y * 64, d0 = blockIdx.x * 64;
    __shared__ __align__(16) float Qs2[64][128];   // [dh][2b] dup'd, pre-scaled 1/8
    __shared__ __align__(16) float Ws[64][64];     // [dh][d]
    int tid = threadIdx.x;

    {
        int lr = tid >> 2, lk = (tid & 3) << 2;
        const float* q0 = g_qp + (size_t)(b0 + lr) * kD + h * kDH;
        const float* bqh = bq + h * kDH;
#pragma unroll
        for (int c = 0; c < 4; c++) {
            float4 v = *(const float4*)(bqh + lk + c * 16);
#pragma unroll
            for (int p = 0; p < 4; p++) {
                float4 vp = *(const float4*)(q0 + (size_t)p * kB * kD + lk + c * 16);
                v.x += vp.x; v.y += vp.y; v.z += vp.z; v.w += vp.w;
            }
            int cc = lk + c * 16;
            *(unsigned long long*)&Qs2[cc + 0][2 * lr] = dup2(0.125f * v.x);
            *(unsigned long long*)&Qs2[cc + 1][2 * lr] = dup2(0.125f * v.y);
            *(unsigned long long*)&Qs2[cc + 2][2 * lr] = dup2(0.125f * v.z);
            *(unsigned long long*)&Qs2[cc + 3][2 * lr] = dup2(0.125f * v.w);
        }
    }
    {
        int wr = tid >> 2, wc = (tid & 3) << 2;
        const float* wrow = wk + (size_t)(h * kDH + wr) * kD + d0;
#pragma unroll
        for (int c = 0; c < 4; c++)
            *(float4*)&Ws[wr][wc + c * 16] = *(const float4*)(wrow + wc + c * 16);
    }
    __syncthreads();

    int tx = tid & 15, ty = tid >> 4;
    unsigned long long acc[4][2] = {};
#pragma unroll 8
    for (int k = 0; k < 64; k++) {
        ulonglong2 ap0 = *(const ulonglong2*)&Qs2[k][ty * 8];
        ulonglong2 ap1 = *(const ulonglong2*)&Qs2[k][ty * 8 + 4];
        ulonglong2 bp  = *(const ulonglong2*)&Ws[k][tx * 4];
        fma2(acc[0][0], ap0.x, bp.x); fma2(acc[0][1], ap0.x, bp.y);
        fma2(acc[1][0], ap0.y, bp.x); fma2(acc[1][1], ap0.y, bp.y);
        fma2(acc[2][0], ap1.x, bp.x); fma2(acc[2][1], ap1.x, bp.y);
        fma2(acc[3][0], ap1.y, bp.x); fma2(acc[3][1], ap1.y, bp.y);
    }
#pragma unroll
    for (int i = 0; i < 4; i++) {
        float2 c0 = unpack2(acc[i][0]);
        float2 c1 = unpack2(acc[i][1]);
        *(float4*)&g_qt[(size_t)(b0 + ty * 4 + i) * (kH * kD) + (size_t)h * kD + d0 + tx * 4]
            = make_float4(c0.x, c0.y, c1.x, c1.y);
    }
}

// ----- ctx split-K x4: ctx_p[kc][b, h*64+dh] = tctx[b,h,kc-qtr] @ Wv_h^T -------
__global__ void __launch_bounds__(256)
k_ctx(const float* __restrict__ wv) {
    __shared__ __align__(16) float As2[16][128];
    __shared__ __align__(16) float Bs[16][64];
    int kc = blockIdx.x, b0 = blockIdx.y * 64, h = blockIdx.z;
    const float* A = g_tctx + (size_t)b0 * (kH * kD) + (size_t)h * kD + kc * 128;
    const float* B = wv + (size_t)h * kDH * kD + kc * 128;
    float* C = g_ctxp + (size_t)kc * kB * kD + (size_t)b0 * kD + (size_t)h * kDH;
    gemm_core<1>(A, 0, nullptr, kH * kD, B, kD, C, kD, 128, As2, Bs);
}

// ----- merged: corr split-K x2 (blocks 0..127) + nsims mem-half (128..255) -----
__global__ void __launch_bounds__(256)
k_corr_nsims(const float* __restrict__ opw, const float* __restrict__ bv) {
    __shared__ __align__(16) float As2[16][128];
    __shared__ __align__(16) float Bs[16][64];
    if (blockIdx.x < 128) {
        int bx = blockIdx.x;
        int kc = bx >> 6, yt = (bx >> 3) & 7, xt = bx & 7;
        const float* A = g_ctxp + (size_t)yt * 64 * kD + kc * 256;
        const float* B = opw + (size_t)xt * 64 * kD + kc * 256;
        float* C = g_corr + (size_t)kc * kB * kD + (size_t)yt * 64 * kD + xt * 64;
        gemm_core<4>(A, (size_t)kB * kD, bv + kc * 256, kD, B, kD, C, kD, 256, As2, Bs);
    } else {
        int idx = blockIdx.x - 128;            // 0..127
        int kc = idx >> 6, yt = (idx >> 3) & 7, xt = idx & 7;
        const float* A = g_vn + (size_t)yt * 64 * kD + kc * 256;
        const float* B = g_negs + (size_t)(kB + xt * 64) * kD + kc * 256;
        float* C = g_nsims + (size_t)kc * kB * kNegC + (size_t)yt * 64 * kNegC
                 + kB + xt * 64;
        gemm_core<1>(A, 0, nullptr, kD, B, kD, C, kNegC, 256, As2, Bs);
    }
}

// ----- attention stage 1: sims + sort/cluster + logits + softmax -> g_attn -----
__global__ void __launch_bounds__(256, 2)
k_attn1(const float* __restrict__ text, float* __restrict__ out_cs) {
    __shared__ float sdot[kM], sss[kM];
    __shared__ float sims[128];
    __shared__ __align__(16) float attn2[kM][kH];
    int b = blockIdx.x, t = threadIdx.x;
    int w = t >> 5, lane = t & 31;                  // 8 warps

    const float4* qt4  = (const float4*)(g_qt + (size_t)b * kH * kD);
    const float4* vn4  = (const float4*)(g_vn + (size_t)b * kD);
    const float4* trow = (const float4*)(text + (size_t)b * kM * kD);

#pragma unroll 1
    for (int half = 0; half < 2; half++) {
        float qa[kH][8];
#pragma unroll
        for (int h = 0; h < kH; h++)
#pragma unroll
            for (int j = 0; j < 2; j++) {
                float4 v = qt4[h * 128 + half * 64 + lane + 32 * j];
                qa[h][j * 4 + 0] = v.x; qa[h][j * 4 + 1] = v.y;
                qa[h][j * 4 + 2] = v.z; qa[h][j * 4 + 3] = v.w;
            }
        float vnr[8];
#pragma unroll
        for (int j = 0; j < 2; j++) {
            float4 v = vn4[half * 64 + lane + 32 * j];
            vnr[j * 4 + 0] = v.x; vnr[j * 4 + 1] = v.y;
            vnr[j * 4 + 2] = v.z; vnr[j * 4 + 3] = v.w;
        }

        float4 pre[2];
        {
            const float4* r = trow + (size_t)w * 128 + half * 64;
            pre[0] = r[lane]; pre[1] = r[lane + 32];
        }
        for (int m = w; m < kM; m += 8) {
            float tx[8];
            tx[0] = pre[0].x; tx[1] = pre[0].y; tx[2] = pre[0].z; tx[3] = pre[0].w;
            tx[4] = pre[1].x; tx[5] = pre[1].y; tx[6] = pre[1].z; tx[7] = pre[1].w;
            if (m + 8 < kM) {
                const float4* r = trow + (size_t)(m + 8) * 128 + half * 64;
                pre[0] = r[lane]; pre[1] = r[lane + 32];
            }
            float dot = 0.f, ss = 0.f, a[kH] = {};
#pragma unroll
            for (int i = 0; i < 8; i++) {
                float tv = tx[i];
                dot += vnr[i] * tv; ss += tv * tv;
#pragma unroll
                for (int h = 0; h < kH; h++) a[h] += qa[h][i] * tv;
            }
            dot = warp_sum(dot); ss = warp_sum(ss);
#pragma unroll
            for (int h = 0; h < kH; h++) a[h] = warp_sum(a[h]);
            if (lane == 0) {
                if (half == 0) {
                    sdot[m] = dot; sss[m] = ss;
#pragma unroll
                    for (int h = 0; h < kH; h++) attn2[m][h] = a[h];
                } else {
                    sdot[m] += dot; sss[m] += ss;
#pragma unroll
                    for (int h = 0; h < kH; h++) attn2[m][h] += a[h];
                }
            }
        }
    }
    __syncthreads();

    if (t < kM) sims[t] = sdot[t] / fmaxf(sqrtf(sss[t]), kEps);
    else if (t < 128) sims[t] = -1e30f;
    __syncthreads();

    for (int k = 2; k <= 128; k <<= 1)
        for (int j = k >> 1; j > 0; j >>= 1) {
            if (t < 128) {
                int ixj = t ^ j;
                if (ixj > t) {
                    float a = sims[t], c = sims[ixj];
                    bool up = ((t & k) == 0);
                    if ((a > c) == up) { sims[t] = c; sims[ixj] = a; }
                }
            }
            __syncthreads();
        }

    if (t < kM) {
        float v = sims[127 - t];
        float mean = warp_sum(v) * (1.0f / 32.0f);
        float dv = v - mean;
        float var = warp_sum(dv * dv) * (1.0f / 31.0f);
        if (lane == 0) out_cs[b * kNC + (t >> 5)] = mean / (sqrtf(var) + 1e-6f);
    }

    {
        int h = w;
        float v0 = attn2[lane][h], v1 = attn2[lane + 32][h], v2 = attn2[lane + 64][h];
        float mx = warp_max(fmaxf(v0, fmaxf(v1, v2)));
        v0 = expf(v0 - mx); v1 = expf(v1 - mx); v2 = expf(v2 - mx);
        float inv = 1.0f / warp_sum(v0 + v1 + v2);
        float* ab = g_attn + (size_t)b * kM * kH + h;
        ab[(size_t)lane * kH]        = v0 * inv;
        ab[(size_t)(lane + 32) * kH] = v1 * inv;
        ab[(size_t)(lane + 64) * kH] = v2 * inv;
    }
}

// ----- attention stage 2: tctx[b,h,4t..4t+3] = sum_m attn[b,m,h]*text[b,m,.] ---
// 128 threads, each owns a float4 d-quad; grid kB.
__global__ void __launch_bounds__(128)
k_attn2(const float* __restrict__ text) {
    __shared__ __align__(16) float sat[kM * kH];    // 768 floats
    int b = blockIdx.x, t = threadIdx.x;            // 128 threads
    {
        const float* ab = g_attn + (size_t)b * kM * kH;
        for (int i = t; i < kM * kH; i += 128) sat[i] = ab[i];
    }
    __syncthreads();

    const float4* tp = (const float4*)(text + (size_t)b * kM * kD) + t;
    float4 acc[kH] = {};
#pragma unroll 8
    for (int m = 0; m < kM; m++) {
        float4 tv = tp[(size_t)m * 128];
        float4 a0 = *(const float4*)&sat[m * kH];
        float4 a1 = *(const float4*)&sat[m * kH + 4];
        acc[0].x += a0.x * tv.x; acc[0].y += a0.x * tv.y; acc[0].z += a0.x * tv.z; acc[0].w += a0.x * tv.w;
        acc[1].x += a0.y * tv.x; acc[1].y += a0.y * tv.y; acc[1].z += a0.y * tv.z; acc[1].w += a0.y * tv.w;
        acc[2].x += a0.z * tv.x; acc[2].y += a0.z * tv.y; acc[2].z += a0.z * tv.z; acc[2].w += a0.z * tv.w;
        acc[3].x += a0.w * tv.x; acc[3].y += a0.w * tv.y; acc[3].z += a0.w * tv.z; acc[3].w += a0.w * tv.w;
        acc[4].x += a1.x * tv.x; acc[4].y += a1.x * tv.y; acc[4].z += a1.x * tv.z; acc[4].w += a1.x * tv.w;
        acc[5].x += a1.y * tv.x; acc[5].y += a1.y * tv.y; acc[5].z += a1.y * tv.z; acc[5].w += a1.y * tv.w;
        acc[6].x += a1.z * tv.x; acc[6].y += a1.z * tv.y; acc[6].z += a1.z * tv.z; acc[6].w += a1.z * tv.w;
        acc[7].x += a1.w * tv.x; acc[7].y += a1.w * tv.y; acc[7].z += a1.w * tv.z; acc[7].w += a1.w * tv.w;
    }
    float* tb = g_tctx + (size_t)b * kH * kD;
#pragma unroll
    for (int h = 0; h < kH; h++) ((float4*)(tb + h * kD))[t] = acc[h];
}

// ----- combine corr partials + opb, copy to d_out, normalize, pos_sim ---------
__global__ void k_cn_pos(float* __restrict__ out_corr, const float* __restrict__ opb) {
    int b = blockIdx.x, t = threadIdx.x;  // 256
    const float* x0 = g_corr + (size_t)b * kD;
    const float* x1 = g_corr + (size_t)kB * kD + (size_t)b * kD;
    const float* vnb = g_vn + (size_t)b * kD;
    float vals[2];
    float ss = 0.f, dt = 0.f;
#pragma unroll
    for (int j = 0; j < 2; j++) {
        int i = t + j * 256;
        float v = x0[i] + x1[i] + opb[i];
        vals[j] = v;
        out_corr[(size_t)b * kD + i] = v;
        ss += v * v; dt += vnb[i] * v;
    }
    __shared__ float rs[8], rd[8];
    ss = warp_sum(ss); dt = warp_sum(dt);
    if ((t & 31) == 0) { rs[t >> 5] = ss; rd[t >> 5] = dt; }
    __syncthreads();
    float s2 = rs[0] + rs[1] + rs[2] + rs[3] + rs[4] + rs[5] + rs[6] + rs[7];
    float d2 = rd[0] + rd[1] + rd[2] + rd[3] + rd[4] + rd[5] + rd[6] + rd[7];
    float inv = 1.0f / fmaxf(sqrtf(s2), kEps);
    if (t == 0) g_pos[b] = d2 * inv;
#pragma unroll
    for (int j = 0; j < 2; j++)
        g_negs[(size_t)b * kD + t + j * 256] = vals[j] * inv;
}

// ----- warp-per-b top-5 (cn sims count twice) + loss, atomic accumulate --------
__device__ __forceinline__ void ins5(float (&t5)[5], float v) {
    if (v > t5[4]) {
        t5[4] = v;
        if (t5[4] > t5[3]) { float tm = t5[3]; t5[3] = t5[4]; t5[4] = tm; }
        if (t5[3] > t5[2]) { float tm = t5[2]; t5[2] = t5[3]; t5[3] = tm; }
        if (t5[2] > t5[1]) { float tm = t5[1]; t5[1] = t5[2]; t5[2] = tm; }
        if (t5[1] > t5[0]) { float tm = t5[0]; t5[0] = t5[1]; t5[1] = tm; }
    }
}
__global__ void __launch_bounds__(512)
k_loss(const float* __restrict__ tpl, const float* __restrict__ tnl,
       float* __restrict__ out_loss) {
    int b = blockIdx.x * 16 + (threadIdx.x >> 5);
    int lane = threadIdx.x & 31;
    const float* ns0 = g_nsims + (size_t)b * kNegC;
    const float* ns1 = ns0 + (size_t)kB * kNegC;
    float t5[5] = {-1e30f, -1e30f, -1e30f, -1e30f, -1e30f};
    for (int i = lane; i < 512; i += 32) {      // cn sims: multiplicity 2
        float v = ns0[i] + ns1[i];
        ins5(t5, v); ins5(t5, v);
    }
    for (int i = 512 + lane; i < 1024; i += 32) // mem sims
        ins5(t5, ns0[i] + ns1[i]);

    float tau_n = expf(tnl[0]);
    int ptr = 0;
    float neg = 0.f;
#pragma unroll
    for (int r = 0; r < 5; r++) {
        float mine = (ptr == 0) ? t5[0] : (ptr == 1) ? t5[1] : (ptr == 2) ? t5[2]
                   : (ptr == 3) ? t5[3] : (ptr == 4) ? t5[4] : -1e30f;
        float mx = warp_max(mine);
        unsigned bal = __ballot_sync(0xffffffffu, mine == mx);
        if (lane == (__ffs(bal) - 1)) ptr++;
        neg += expf(mx / tau_n);
    }
    if (lane == 0) {
        float tau_p = expf(tpl[0]);
        float pos = expf(g_pos[b] / tau_p);
        atomicAdd(out_loss, -logf(pos / (pos + neg + 1e-8f)) * (1.0f / (float)kB));
    }
}

// ---------------------------------------------------------------------------
extern "C" void kernel_launch(void* const* d_in, const int* in_sizes, int n_in,
                              void* d_out, int out_size) {
    const float* vis  = (const float*)d_in[0];
    const float* text = (const float*)d_in[1];
    const float* ipw  = (const float*)d_in[2];
    const float* ipb  = (const float*)d_in[3];
    const float* opw  = (const float*)d_in[4];
    const float* opb  = (const float*)d_in[5];
    const float* tmem = (const float*)d_in[6];
    const float* tpl  = (const float*)d_in[7];
    const float* tnl  = (const float*)d_in[8];

    float* out      = (float*)d_out;
    float* out_corr = out + 1;
    float* out_cs   = out + 1 + kB * kD;

    float *p_vn, *p_negs, *p_nsims;
    cudaGetSymbolAddress((void**)&p_vn,    g_vn);
    cudaGetSymbolAddress((void**)&p_negs,  g_negs);
    cudaGetSymbolAddress((void**)&p_nsims, g_nsims);

    // 1. qproj split-K x4 + vis/mem row norms + loss-accumulator init
    k_pre_qproj<<<256 + 2 * kB, 256>>>(vis, tmem, ipw, out);
    // 2. qt = (1/8)(Σ4 q partials + bq)_h @ Wk_h   (512 blocks)
    k_qt_kernel<<<dim3(kD / 64, kB / 64, kH), 256>>>(ipw + (size_t)kD * kD, ipb);
    // 3. attention stage 1 -> g_attn (512 blocks)
    k_attn1<<<kB, 256>>>(text, out_cs);
    // 4. attention stage 2 -> g_tctx (512 blocks, float4/thread, 128 threads)
    k_attn2<<<kB, 128>>>(text);
    // 5. ctx split-K x4 per head (256 blocks)
    k_ctx<<<dim3(4, kB / 64, kH), 256>>>(ipw + 2 * (size_t)kD * kD);
    // 6. corr split-K x2 (128 blocks) + nsims mem-half (128 blocks), homogeneous
    k_corr_nsims<<<256, 256>>>(opw, ipb + 2 * kD);
    // 7. combine corr partials + opb -> d_out, normalize into g_negs[0:512], pos
    k_cn_pos<<<kB, 256>>>(out_corr, opb);
    // 8. nsims cn-half split-K x2 (128 blocks)
    k_gemm_nt<1><<<dim3(kB / 64, kB / 64, 2), 256>>>(
        p_vn, 0, nullptr, kD, 256,
        p_negs, kD, 256, p_nsims, kNegC, kB * kNegC, 256);
    // 9. top-5 + per-row loss, atomic mean into out[0]
    k_loss<<<kB / 16, 512>>>(tpl, tnl, out);
}

// round 16
// speedup vs baseline: 1.0297x; 1.0297x over previous
#include <cuda_runtime.h>

// ---------------------------------------------------------------------------
// DiscriminativeClueCorrection — R14 configuration (verified best, 182.4 us).
// fp32 FFMA2 dup-A GEMMs (split-K, free combines at consumers), two-stage
// attention, homogeneous corr+nsims-mem co-launch, atomic loss reduction.
// Output layout (float32): [loss(1)] [corrected(512*512)] [cluster_scores(512*3)]
// ---------------------------------------------------------------------------

constexpr int kB    = 512;
constexpr int kM    = 96;
constexpr int kD    = 512;
constexpr int kH    = 8;
constexpr int kDH   = 64;
constexpr int kNC   = 3;
constexpr int kNegC = 1024;
constexpr float kEps = 1e-8f;

// ----- device scratch --------------------------------------------------------
__device__ float g_vn   [kB * kD];
__device__ float g_qp   [4 * kB * kD];      // qproj split-K x4 partials
__device__ float g_qt   [kB * kH * kD];     // per-b transformed key weights (×1/8)
__device__ float g_attn [kB * kM * kH];     // softmaxed attention probs
__device__ float g_tctx [kB * kH * kD];
__device__ float g_ctxp [4 * kB * kD];      // ctx split-K x4 partials
__device__ float g_corr [2 * kB * kD];      // corr split-K x2 partials
__device__ float g_pos  [kB];
__device__ float g_negs [kNegC * kD];
__device__ float g_nsims[2 * kB * kNegC];   // nsims split-K x2 partials

__device__ __forceinline__ float warp_sum(float v) {
#pragma unroll
    for (int o = 16; o > 0; o >>= 1) v += __shfl_xor_sync(0xffffffffu, v, o);
    return v;
}
__device__ __forceinline__ float warp_max(float v) {
#pragma unroll
    for (int o = 16; o > 0; o >>= 1) v = fmaxf(v, __shfl_xor_sync(0xffffffffu, v, o));
    return v;
}

// ----- f32x2 packed helpers ---------------------------------------------------
__device__ __forceinline__ unsigned long long dup2(float v) {
    unsigned long long r;
    asm("mov.b64 %0, {%1,%1};" : "=l"(r) : "f"(v));
    return r;
}
__device__ __forceinline__ void fma2(unsigned long long& acc, unsigned long long a,
                                     unsigned long long b) {
    asm("fma.rn.f32x2 %0, %1, %2, %0;" : "+l"(acc) : "l"(a), "l"(b));
}
__device__ __forceinline__ float2 unpack2(unsigned long long v) {
    float2 f;
    asm("mov.b64 {%0,%1}, %2;" : "=f"(f.x), "=f"(f.y) : "l"(v));
    return f;
}

// ----- shared GEMM core: 64x64 tile, BK=16, dup-A FFMA2 (R4-proven) -----------
template <int NPART>
__device__ __forceinline__ void gemm_core(
    const float* __restrict__ A, size_t aPartStride,
    const float* __restrict__ abias, int lda,
    const float* __restrict__ Bm, int ldb,
    float* __restrict__ C, int ldc, int K,
    float (&As2)[16][128], float (&Bs)[16][64])
{
    int tid = threadIdx.x;
    int tx = tid & 15, ty = tid >> 4;
    int lr = tid >> 2, lk = (tid & 3) << 2;

    const float* Aload = A + (size_t)lr * lda + lk;
    const float* Bload = Bm + (size_t)lr * ldb + lk;

    auto loadA = [&](int k0) -> float4 {
        float4 r = *(const float4*)(Aload + k0);
#pragma unroll
        for (int p = 1; p < NPART; p++) {
            float4 tq = *(const float4*)(Aload + p * aPartStride + k0);
            r.x += tq.x; r.y += tq.y; r.z += tq.z; r.w += tq.w;
        }
        if (abias) {
            float4 tq = *(const float4*)(abias + k0 + lk);
            r.x += tq.x; r.y += tq.y; r.z += tq.z; r.w += tq.w;
        }
        return r;
    };

    float4 a4 = loadA(0);
    float4 b4 = *(const float4*)Bload;

    unsigned long long acc[4][2] = {};
    for (int k0 = 0; k0 < K; k0 += 16) {
        *(unsigned long long*)&As2[lk + 0][2 * lr] = dup2(a4.x);
        *(unsigned long long*)&As2[lk + 1][2 * lr] = dup2(a4.y);
        *(unsigned long long*)&As2[lk + 2][2 * lr] = dup2(a4.z);
        *(unsigned long long*)&As2[lk + 3][2 * lr] = dup2(a4.w);
        Bs[lk + 0][lr] = b4.x; Bs[lk + 1][lr] = b4.y;
        Bs[lk + 2][lr] = b4.z; Bs[lk + 3][lr] = b4.w;
        __syncthreads();
        if (k0 + 16 < K) {
            a4 = loadA(k0 + 16);
            b4 = *(const float4*)(Bload + k0 + 16);
        }
#pragma unroll
        for (int k = 0; k < 16; k++) {
            ulonglong2 ap0 = *(const ulonglong2*)&As2[k][ty * 8];
            ulonglong2 ap1 = *(const ulonglong2*)&As2[k][ty * 8 + 4];
            ulonglong2 bp  = *(const ulonglong2*)&Bs[k][tx * 4];
            fma2(acc[0][0], ap0.x, bp.x); fma2(acc[0][1], ap0.x, bp.y);
            fma2(acc[1][0], ap0.y, bp.x); fma2(acc[1][1], ap0.y, bp.y);
            fma2(acc[2][0], ap1.x, bp.x); fma2(acc[2][1], ap1.x, bp.y);
            fma2(acc[3][0], ap1.y, bp.x); fma2(acc[3][1], ap1.y, bp.y);
        }
        __syncthreads();
    }
#pragma unroll
    for (int i = 0; i < 4; i++) {
        float2 c0 = unpack2(acc[i][0]);
        float2 c1 = unpack2(acc[i][1]);
        *(float4*)&C[(size_t)(ty * 4 + i) * ldc + tx * 4]
            = make_float4(c0.x, c0.y, c1.x, c1.y);
    }
}

// ----- generic NT GEMM wrapper --------------------------------------------------
template <int NPART>
__global__ void __launch_bounds__(256)
k_gemm_nt(const float* __restrict__ A, size_t aPartStride,
          const float* __restrict__ abias, int lda, int sAz,
          const float* __restrict__ Bm, int ldb, int sBz,
          float* __restrict__ C, int ldc, int sCz, int K) {
    __shared__ __align__(16) float As2[16][128];
    __shared__ __align__(16) float Bs[16][64];
    size_t aoff = (size_t)blockIdx.z * sAz + (size_t)blockIdx.y * 64 * lda;
    const float* Ar  = A + aoff;
    const float* abr = abias ? abias + (size_t)blockIdx.z * sAz : nullptr;
    const float* Br  = Bm + (size_t)blockIdx.z * sBz + (size_t)blockIdx.x * 64 * ldb;
    float* Cr = C + (size_t)blockIdx.z * sCz + (size_t)blockIdx.y * 64 * ldc
                  + (size_t)blockIdx.x * 64;
    gemm_core<NPART>(Ar, aPartStride, abr, lda, Br, ldb, Cr, ldc, K, As2, Bs);
}

// ----- merged: qproj split-K x4 (blocks 0..255) + row norms (256..1279) --------
__global__ void __launch_bounds__(256)
k_pre_qproj(const float* __restrict__ vis, const float* __restrict__ tmem,
            const float* __restrict__ ipw, float* __restrict__ out_loss) {
    __shared__ __align__(16) float As2[16][128];
    __shared__ __align__(16) float Bs[16][64];
    __shared__ float red[8];
    if (blockIdx.x < 256) {
        int bx = blockIdx.x;
        int kc = bx >> 6, yt = (bx >> 3) & 7, xt = bx & 7;
        const float* A = vis + (size_t)yt * 64 * kD + kc * 128;
        const float* B = ipw + (size_t)xt * 64 * kD + kc * 128;
        float* C = g_qp + (size_t)kc * kB * kD + (size_t)yt * 64 * kD + xt * 64;
        gemm_core<1>(A, 0, nullptr, kD, B, kD, C, kD, 128, As2, Bs);
    } else {
        int idx = blockIdx.x - 256;           // 0..1023
        int t = threadIdx.x;
        if (blockIdx.x == 256 && t == 0) out_loss[0] = 0.f;   // init loss accumulator
        const float* x;
        float* outp;
        if (idx < kB) { x = vis + (size_t)idx * kD;  outp = g_vn + (size_t)idx * kD; }
        else          { x = tmem + (size_t)idx * kD; outp = g_negs + (size_t)idx * kD; }
        float ss = 0.f;
        for (int i = t; i < kD; i += 256) { float v = x[i]; ss += v * v; }
        ss = warp_sum(ss);
        if ((t & 31) == 0) red[t >> 5] = ss;
        __syncthreads();
        float tot = red[0] + red[1] + red[2] + red[3] + red[4] + red[5] + red[6] + red[7];
        float inv = 1.0f / fmaxf(sqrtf(tot), kEps);
        for (int i = t; i < kD; i += 256) outp[i] = x[i] * inv;
    }
}

// ----- qt[b,h,d] = (1/8) * sum_dh (Σ4 q partials + bq)[b,h,dh] * Wk[.,d] -------
__global__ void __launch_bounds__(256)
k_qt_kernel(const float* __restrict__ wk, const float* __restrict__ bq) {
    int h = blockIdx.z, b0 = blockIdx.y * 64, d0 = blockIdx.x * 64;
    __shared__ __align__(16) float Qs2[64][128];   // [dh][2b] dup'd, pre-scaled 1/8
    __shared__ __align__(16) float Ws[64][64];     // [dh][d]
    int tid = threadIdx.x;

    {
        int lr = tid >> 2, lk = (tid & 3) << 2;
        const float* q0 = g_qp + (size_t)(b0 + lr) * kD + h * kDH;
        const float* bqh = bq + h * kDH;
#pragma unroll
        for (int c = 0; c < 4; c++) {
            float4 v = *(const float4*)(bqh + lk + c * 16);
#pragma unroll
            for (int p = 0; p < 4; p++) {
                float4 vp = *(const float4*)(q0 + (size_t)p * kB * kD + lk + c * 16);
                v.x += vp.x; v.y += vp.y; v.z += vp.z; v.w += vp.w;
            }
            int cc = lk + c * 16;
            *(unsigned long long*)&Qs2[cc + 0][2 * lr] = dup2(0.125f * v.x);
            *(unsigned long long*)&Qs2[cc + 1][2 * lr] = dup2(0.125f * v.y);
            *(unsigned long long*)&Qs2[cc + 2][2 * lr] = dup2(0.125f * v.z);
            *(unsigned long long*)&Qs2[cc + 3][2 * lr] = dup2(0.125f * v.w);
        }
    }
    {
        int wr = tid >> 2, wc = (tid & 3) << 2;
        const float* wrow = wk + (size_t)(h * kDH + wr) * kD + d0;
#pragma unroll
        for (int c = 0; c < 4; c++)
            *(float4*)&Ws[wr][wc + c * 16] = *(const float4*)(wrow + wc + c * 16);
    }
    __syncthreads();

    int tx = tid & 15, ty = tid >> 4;
    unsigned long long acc[4][2] = {};
#pragma unroll 8
    for (int k = 0; k < 64; k++) {
        ulonglong2 ap0 = *(const ulonglong2*)&Qs2[k][ty * 8];
        ulonglong2 ap1 = *(const ulonglong2*)&Qs2[k][ty * 8 + 4];
        ulonglong2 bp  = *(const ulonglong2*)&Ws[k][tx * 4];
        fma2(acc[0][0], ap0.x, bp.x); fma2(acc[0][1], ap0.x, bp.y);
        fma2(acc[1][0], ap0.y, bp.x); fma2(acc[1][1], ap0.y, bp.y);
        fma2(acc[2][0], ap1.x, bp.x); fma2(acc[2][1], ap1.x, bp.y);
        fma2(acc[3][0], ap1.y, bp.x); fma2(acc[3][1], ap1.y, bp.y);
    }
#pragma unroll
    for (int i = 0; i < 4; i++) {
        float2 c0 = unpack2(acc[i][0]);
        float2 c1 = unpack2(acc[i][1]);
        *(float4*)&g_qt[(size_t)(b0 + ty * 4 + i) * (kH * kD) + (size_t)h * kD + d0 + tx * 4]
            = make_float4(c0.x, c0.y, c1.x, c1.y);
    }
}

// ----- ctx split-K x4: ctx_p[kc][b, h*64+dh] = tctx[b,h,kc-qtr] @ Wv_h^T -------
__global__ void __launch_bounds__(256)
k_ctx(const float* __restrict__ wv) {
    __shared__ __align__(16) float As2[16][128];
    __shared__ __align__(16) float Bs[16][64];
    int kc = blockIdx.x, b0 = blockIdx.y * 64, h = blockIdx.z;
    const float* A = g_tctx + (size_t)b0 * (kH * kD) + (size_t)h * kD + kc * 128;
    const float* B = wv + (size_t)h * kDH * kD + kc * 128;
    float* C = g_ctxp + (size_t)kc * kB * kD + (size_t)b0 * kD + (size_t)h * kDH;
    gemm_core<1>(A, 0, nullptr, kH * kD, B, kD, C, kD, 128, As2, Bs);
}

// ----- merged: corr split-K x2 (blocks 0..127) + nsims mem-half (128..255) -----
__global__ void __launch_bounds__(256)
k_corr_nsims(const float* __restrict__ opw, const float* __restrict__ bv) {
    __shared__ __align__(16) float As2[16][128];
    __shared__ __align__(16) float Bs[16][64];
    if (blockIdx.x < 128) {
        int bx = blockIdx.x;
        int kc = bx >> 6, yt = (bx >> 3) & 7, xt = bx & 7;
        const float* A = g_ctxp + (size_t)yt * 64 * kD + kc * 256;
        const float* B = opw + (size_t)xt * 64 * kD + kc * 256;
        float* C = g_corr + (size_t)kc * kB * kD + (size_t)yt * 64 * kD + xt * 64;
        gemm_core<4>(A, (size_t)kB * kD, bv + kc * 256, kD, B, kD, C, kD, 256, As2, Bs);
    } else {
        int idx = blockIdx.x - 128;            // 0..127
        int kc = idx >> 6, yt = (idx >> 3) & 7, xt = idx & 7;
        const float* A = g_vn + (size_t)yt * 64 * kD + kc * 256;
        const float* B = g_negs + (size_t)(kB + xt * 64) * kD + kc * 256;
        float* C = g_nsims + (size_t)kc * kB * kNegC + (size_t)yt * 64 * kNegC
                 + kB + xt * 64;
        gemm_core<1>(A, 0, nullptr, kD, B, kD, C, kNegC, 256, As2, Bs);
    }
}

// ----- attention stage 1: sims + sort/cluster + logits + softmax -> g_attn -----
__global__ void __launch_bounds__(256, 2)
k_attn1(const float* __restrict__ text, float* __restrict__ out_cs) {
    __shared__ float sdot[kM], sss[kM];
    __shared__ float sims[128];
    __shared__ __align__(16) float attn2[kM][kH];
    int b = blockIdx.x, t = threadIdx.x;
    int w = t >> 5, lane = t & 31;                  // 8 warps

    const float4* qt4  = (const float4*)(g_qt + (size_t)b * kH * kD);
    const float4* vn4  = (const float4*)(g_vn + (size_t)b * kD);
    const float4* trow = (const float4*)(text + (size_t)b * kM * kD);

#pragma unroll 1
    for (int half = 0; half < 2; half++) {
        float qa[kH][8];
#pragma unroll
        for (int h = 0; h < kH; h++)
#pragma unroll
            for (int j = 0; j < 2; j++) {
                float4 v = qt4[h * 128 + half * 64 + lane + 32 * j];
                qa[h][j * 4 + 0] = v.x; qa[h][j * 4 + 1] = v.y;
                qa[h][j * 4 + 2] = v.z; qa[h][j * 4 + 3] = v.w;
            }
        float vnr[8];
#pragma unroll
        for (int j = 0; j < 2; j++) {
            float4 v = vn4[half * 64 + lane + 32 * j];
            vnr[j * 4 + 0] = v.x; vnr[j * 4 + 1] = v.y;
            vnr[j * 4 + 2] = v.z; vnr[j * 4 + 3] = v.w;
        }

        float4 pre[2];
        {
            const float4* r = trow + (size_t)w * 128 + half * 64;
            pre[0] = r[lane]; pre[1] = r[lane + 32];
        }
        for (int m = w; m < kM; m += 8) {
            float tx[8];
            tx[0] = pre[0].x; tx[1] = pre[0].y; tx[2] = pre[0].z; tx[3] = pre[0].w;
            tx[4] = pre[1].x; tx[5] = pre[1].y; tx[6] = pre[1].z; tx[7] = pre[1].w;
            if (m + 8 < kM) {
                const float4* r = trow + (size_t)(m + 8) * 128 + half * 64;
                pre[0] = r[lane]; pre[1] = r[lane + 32];
            }
            float dot = 0.f, ss = 0.f, a[kH] = {};
#pragma unroll
            for (int i = 0; i < 8; i++) {
                float tv = tx[i];
                dot += vnr[i] * tv; ss += tv * tv;
#pragma unroll
                for (int h = 0; h < kH; h++) a[h] += qa[h][i] * tv;
            }
            dot = warp_sum(dot); ss = warp_sum(ss);
#pragma unroll
            for (int h = 0; h < kH; h++) a[h] = warp_sum(a[h]);
            if (lane == 0) {
                if (half == 0) {
                    sdot[m] = dot; sss[m] = ss;
#pragma unroll
                    for (int h = 0; h < kH; h++) attn2[m][h] = a[h];
                } else {
                    sdot[m] += dot; sss[m] += ss;
#pragma unroll
                    for (int h = 0; h < kH; h++) attn2[m][h] += a[h];
                }
            }
        }
    }
    __syncthreads();

    if (t < kM) sims[t] = sdot[t] / fmaxf(sqrtf(sss[t]), kEps);
    else if (t < 128) sims[t] = -1e30f;
    __syncthreads();

    for (int k = 2; k <= 128; k <<= 1)
        for (int j = k >> 1; j > 0; j >>= 1) {
            if (t < 128) {
                int ixj = t ^ j;
                if (ixj > t) {
                    float a = sims[t], c = sims[ixj];
                    bool up = ((t & k) == 0);
                    if ((a > c) == up) { sims[t] = c; sims[ixj] = a; }
                }
            }
            __syncthreads();
        }

    if (t < kM) {
        float v = sims[127 - t];
        float mean = warp_sum(v) * (1.0f / 32.0f);
        float dv = v - mean;
        float var = warp_sum(dv * dv) * (1.0f / 31.0f);
        if (lane == 0) out_cs[b * kNC + (t >> 5)] = mean / (sqrtf(var) + 1e-6f);
    }

    {
        int h = w;
        float v0 = attn2[lane][h], v1 = attn2[lane + 32][h], v2 = attn2[lane + 64][h];
        float mx = warp_max(fmaxf(v0, fmaxf(v1, v2)));
        v0 = expf(v0 - mx); v1 = expf(v1 - mx); v2 = expf(v2 - mx);
        float inv = 1.0f / warp_sum(v0 + v1 + v2);
        float* ab = g_attn + (size_t)b * kM * kH + h;
        ab[(size_t)lane * kH]        = v0 * inv;
        ab[(size_t)(lane + 32) * kH] = v1 * inv;
        ab[(size_t)(lane + 64) * kH] = v2 * inv;
    }
}

// ----- attention stage 2: tctx[b,h,2t..2t+1] = sum_m attn[b,m,h]*text[b,m,.] ---
__global__ void __launch_bounds__(256)
k_attn2(const float* __restrict__ text) {
    __shared__ __align__(16) float sat[kM * kH];    // 768 floats
    int b = blockIdx.x, t = threadIdx.x;
    {
        const float* ab = g_attn + (size_t)b * kM * kH;
        for (int i = t; i < kM * kH; i += 256) sat[i] = ab[i];
    }
    __syncthreads();

    const float2* tp = (const float2*)(text + (size_t)b * kM * kD) + t;
    float2 acc[kH] = {};
#pragma unroll 8
    for (int m = 0; m < kM; m++) {
        float2 tv = tp[(size_t)m * 256];
        float4 a0 = *(const float4*)&sat[m * kH];
        float4 a1 = *(const float4*)&sat[m * kH + 4];
        acc[0].x += a0.x * tv.x; acc[0].y += a0.x * tv.y;
        acc[1].x += a0.y * tv.x; acc[1].y += a0.y * tv.y;
        acc[2].x += a0.z * tv.x; acc[2].y += a0.z * tv.y;
        acc[3].x += a0.w * tv.x; acc[3].y += a0.w * tv.y;
        acc[4].x += a1.x * tv.x; acc[4].y += a1.x * tv.y;
        acc[5].x += a1.y * tv.x; acc[5].y += a1.y * tv.y;
        acc[6].x += a1.z * tv.x; acc[6].y += a1.z * tv.y;
        acc[7].x += a1.w * tv.x; acc[7].y += a1.w * tv.y;
    }
    float* tb = g_tctx + (size_t)b * kH * kD;
#pragma unroll
    for (int h = 0; h < kH; h++) ((float2*)(tb + h * kD))[t] = acc[h];
}

// ----- combine corr partials + opb, copy to d_out, normalize, pos_sim ---------
__global__ void k_cn_pos(float* __restrict__ out_corr, const float* __restrict__ opb) {
    int b = blockIdx.x, t = threadIdx.x;  // 256
    const float* x0 = g_corr + (size_t)b * kD;
    const float* x1 = g_corr + (size_t)kB * kD + (size_t)b * kD;
    const float* vnb = g_vn + (size_t)b * kD;
    float vals[2];
    float ss = 0.f, dt = 0.f;
#pragma unroll
    for (int j = 0; j < 2; j++) {
        int i = t + j * 256;
        float v = x0[i] + x1[i] + opb[i];
        vals[j] = v;
        out_corr[(size_t)b * kD + i] = v;
        ss += v * v; dt += vnb[i] * v;
    }
    __shared__ float rs[8], rd[8];
    ss = warp_sum(ss); dt = warp_sum(dt);
    if ((t & 31) == 0) { rs[t >> 5] = ss; rd[t >> 5] = dt; }
    __syncthreads();
    float s2 = rs[0] + rs[1] + rs[2] + rs[3] + rs[4] + rs[5] + rs[6] + rs[7];
    float d2 = rd[0] + rd[1] + rd[2] + rd[3] + rd[4] + rd[5] + rd[6] + rd[7];
    float inv = 1.0f / fmaxf(sqrtf(s2), kEps);
    if (t == 0) g_pos[b] = d2 * inv;
#pragma unroll
    for (int j = 0; j < 2; j++)
        g_negs[(size_t)b * kD + t + j * 256] = vals[j] * inv;
}

// ----- warp-per-b top-5 (cn sims count twice) + loss, atomic accumulate --------
__device__ __forceinline__ void ins5(float (&t5)[5], float v) {
    if (v > t5[4]) {
        t5[4] = v;
        if (t5[4] > t5[3]) { float tm = t5[3]; t5[3] = t5[4]; t5[4] = tm; }
        if (t5[3] > t5[2]) { float tm = t5[2]; t5[2] = t5[3]; t5[3] = tm; }
        if (t5[2] > t5[1]) { float tm = t5[1]; t5[1] = t5[2]; t5[2] = tm; }
        if (t5[1] > t5[0]) { float tm = t5[0]; t5[0] = t5[1]; t5[1] = tm; }
    }
}
__global__ void __launch_bounds__(512)
k_loss(const float* __restrict__ tpl, const float* __restrict__ tnl,
       float* __restrict__ out_loss) {
    int b = blockIdx.x * 16 + (threadIdx.x >> 5);
    int lane = threadIdx.x & 31;
    const float* ns0 = g_nsims + (size_t)b * kNegC;
    const float* ns1 = ns0 + (size_t)kB * kNegC;
    float t5[5] = {-1e30f, -1e30f, -1e30f, -1e30f, -1e30f};
    for (int i = lane; i < 512; i += 32) {      // cn sims: multiplicity 2
        float v = ns0[i] + ns1[i];
        ins5(t5, v); ins5(t5, v);
    }
    for (int i = 512 + lane; i < 1024; i += 32) // mem sims
        ins5(t5, ns0[i] + ns1[i]);

    float tau_n = expf(tnl[0]);
    int ptr = 0;
    float neg = 0.f;
#pragma unroll
    for (int r = 0; r < 5; r++) {
        float mine = (ptr == 0) ? t5[0] : (ptr == 1) ? t5[1] : (ptr == 2) ? t5[2]
                   : (ptr == 3) ? t5[3] : (ptr == 4) ? t5[4] : -1e30f;
        float mx = warp_max(mine);
        unsigned bal = __ballot_sync(0xffffffffu, mine == mx);
        if (lane == (__ffs(bal) - 1)) ptr++;
        neg += expf(mx / tau_n);
    }
    if (lane == 0) {
        float tau_p = expf(tpl[0]);
        float pos = expf(g_pos[b] / tau_p);
        atomicAdd(out_loss, -logf(pos / (pos + neg + 1e-8f)) * (1.0f / (float)kB));
    }
}

// ---------------------------------------------------------------------------
extern "C" void kernel_launch(void* const* d_in, const int* in_sizes, int n_in,
                              void* d_out, int out_size) {
    const float* vis  = (const float*)d_in[0];
    const float* text = (const float*)d_in[1];
    const float* ipw  = (const float*)d_in[2];
    const float* ipb  = (const float*)d_in[3];
    const float* opw  = (const float*)d_in[4];
    const float* opb  = (const float*)d_in[5];
    const float* tmem = (const float*)d_in[6];
    const float* tpl  = (const float*)d_in[7];
    const float* tnl  = (const float*)d_in[8];

    float* out      = (float*)d_out;
    float* out_corr = out + 1;
    float* out_cs   = out + 1 + kB * kD;

    float *p_vn, *p_negs, *p_nsims;
    cudaGetSymbolAddress((void**)&p_vn,    g_vn);
    cudaGetSymbolAddress((void**)&p_negs,  g_negs);
    cudaGetSymbolAddress((void**)&p_nsims, g_nsims);

    // 1. qproj split-K x4 + vis/mem row norms + loss-accumulator init
    k_pre_qproj<<<256 + 2 * kB, 256>>>(vis, tmem, ipw, out);
    // 2. qt = (1/8)(Σ4 q partials + bq)_h @ Wk_h   (512 blocks)
    k_qt_kernel<<<dim3(kD / 64, kB / 64, kH), 256>>>(ipw + (size_t)kD * kD, ipb);
    // 3. attention stage 1 -> g_attn (512 blocks)
    k_attn1<<<kB, 256>>>(text, out_cs);
    // 4. attention stage 2 -> g_tctx (512 blocks, float2/thread)
    k_attn2<<<kB, 256>>>(text);
    // 5. ctx split-K x4 per head (256 blocks)
    k_ctx<<<dim3(4, kB / 64, kH), 256>>>(ipw + 2 * (size_t)kD * kD);
    // 6. corr split-K x2 (128 blocks) + nsims mem-half (128 blocks), homogeneous
    k_corr_nsims<<<256, 256>>>(opw, ipb + 2 * kD);
    // 7. combine corr partials + opb -> d_out, normalize into g_negs[0:512], pos
    k_cn_pos<<<kB, 256>>>(out_corr, opb);
    // 8. nsims cn-half split-K x2 (128 blocks)
    k_gemm_nt<1><<<dim3(kB / 64, kB / 64, 2), 256>>>(
        p_vn, 0, nullptr, kD, 256,
        p_negs, kD, 256, p_nsims, kNegC, kB * kNegC, 256);
    // 9. top-5 + per-row loss, atomic mean into out[0]
    k_loss<<<kB / 16, 512>>>(tpl, tnl, out);
}

// round 17
// speedup vs baseline: 1.0456x; 1.0154x over previous
#include <cuda_runtime.h>

// ---------------------------------------------------------------------------
// DiscriminativeClueCorrection — R14 configuration + nsims-cn split-K x4.
// fp32 FFMA2 dup-A GEMMs (split-K, free combines at consumers), two-stage
// attention, homogeneous corr+nsims-mem co-launch, atomic loss reduction.
// Output layout (float32): [loss(1)] [corrected(512*512)] [cluster_scores(512*3)]
// ---------------------------------------------------------------------------

constexpr int kB    = 512;
constexpr int kM    = 96;
constexpr int kD    = 512;
constexpr int kH    = 8;
constexpr int kDH   = 64;
constexpr int kNC   = 3;
constexpr int kNegC = 1024;
constexpr float kEps = 1e-8f;

// ----- device scratch --------------------------------------------------------
__device__ float g_vn   [kB * kD];
__device__ float g_qp   [4 * kB * kD];      // qproj split-K x4 partials
__device__ float g_qt   [kB * kH * kD];     // per-b transformed key weights (×1/8)
__device__ float g_attn [kB * kM * kH];     // softmaxed attention probs
__device__ float g_tctx [kB * kH * kD];
__device__ float g_ctxp [4 * kB * kD];      // ctx split-K x4 partials
__device__ float g_corr [2 * kB * kD];      // corr split-K x2 partials
__device__ float g_pos  [kB];
__device__ float g_negs [kNegC * kD];
__device__ float g_nsims[4 * kB * kNegC];   // nsims partials (cn: x4, mem: x2)

__device__ __forceinline__ float warp_sum(float v) {
#pragma unroll
    for (int o = 16; o > 0; o >>= 1) v += __shfl_xor_sync(0xffffffffu, v, o);
    return v;
}
__device__ __forceinline__ float warp_max(float v) {
#pragma unroll
    for (int o = 16; o > 0; o >>= 1) v = fmaxf(v, __shfl_xor_sync(0xffffffffu, v, o));
    return v;
}

// ----- f32x2 packed helpers ---------------------------------------------------
__device__ __forceinline__ unsigned long long dup2(float v) {
    unsigned long long r;
    asm("mov.b64 %0, {%1,%1};" : "=l"(r) : "f"(v));
    return r;
}
__device__ __forceinline__ void fma2(unsigned long long& acc, unsigned long long a,
                                     unsigned long long b) {
    asm("fma.rn.f32x2 %0, %1, %2, %0;" : "+l"(acc) : "l"(a), "l"(b));
}
__device__ __forceinline__ float2 unpack2(unsigned long long v) {
    float2 f;
    asm("mov.b64 {%0,%1}, %2;" : "=f"(f.x), "=f"(f.y) : "l"(v));
    return f;
}

// ----- shared GEMM core: 64x64 tile, BK=16, dup-A FFMA2 (R4-proven) -----------
template <int NPART>
__device__ __forceinline__ void gemm_core(
    const float* __restrict__ A, size_t aPartStride,
    const float* __restrict__ abias, int lda,
    const float* __restrict__ Bm, int ldb,
    float* __restrict__ C, int ldc, int K,
    float (&As2)[16][128], float (&Bs)[16][64])
{
    int tid = threadIdx.x;
    int tx = tid & 15, ty = tid >> 4;
    int lr = tid >> 2, lk = (tid & 3) << 2;

    const float* Aload = A + (size_t)lr * lda + lk;
    const float* Bload = Bm + (size_t)lr * ldb + lk;

    auto loadA = [&](int k0) -> float4 {
        float4 r = *(const float4*)(Aload + k0);
#pragma unroll
        for (int p = 1; p < NPART; p++) {
            float4 tq = *(const float4*)(Aload + p * aPartStride + k0);
            r.x += tq.x; r.y += tq.y; r.z += tq.z; r.w += tq.w;
        }
        if (abias) {
            float4 tq = *(const float4*)(abias + k0 + lk);
            r.x += tq.x; r.y += tq.y; r.z += tq.z; r.w += tq.w;
        }
        return r;
    };

    float4 a4 = loadA(0);
    float4 b4 = *(const float4*)Bload;

    unsigned long long acc[4][2] = {};
    for (int k0 = 0; k0 < K; k0 += 16) {
        *(unsigned long long*)&As2[lk + 0][2 * lr] = dup2(a4.x);
        *(unsigned long long*)&As2[lk + 1][2 * lr] = dup2(a4.y);
        *(unsigned long long*)&As2[lk + 2][2 * lr] = dup2(a4.z);
        *(unsigned long long*)&As2[lk + 3][2 * lr] = dup2(a4.w);
        Bs[lk + 0][lr] = b4.x; Bs[lk + 1][lr] = b4.y;
        Bs[lk + 2][lr] = b4.z; Bs[lk + 3][lr] = b4.w;
        __syncthreads();
        if (k0 + 16 < K) {
            a4 = loadA(k0 + 16);
            b4 = *(const float4*)(Bload + k0 + 16);
        }
#pragma unroll
        for (int k = 0; k < 16; k++) {
            ulonglong2 ap0 = *(const ulonglong2*)&As2[k][ty * 8];
            ulonglong2 ap1 = *(const ulonglong2*)&As2[k][ty * 8 + 4];
            ulonglong2 bp  = *(const ulonglong2*)&Bs[k][tx * 4];
            fma2(acc[0][0], ap0.x, bp.x); fma2(acc[0][1], ap0.x, bp.y);
            fma2(acc[1][0], ap0.y, bp.x); fma2(acc[1][1], ap0.y, bp.y);
            fma2(acc[2][0], ap1.x, bp.x); fma2(acc[2][1], ap1.x, bp.y);
            fma2(acc[3][0], ap1.y, bp.x); fma2(acc[3][1], ap1.y, bp.y);
        }
        __syncthreads();
    }
#pragma unroll
    for (int i = 0; i < 4; i++) {
        float2 c0 = unpack2(acc[i][0]);
        float2 c1 = unpack2(acc[i][1]);
        *(float4*)&C[(size_t)(ty * 4 + i) * ldc + tx * 4]
            = make_float4(c0.x, c0.y, c1.x, c1.y);
    }
}

// ----- generic NT GEMM wrapper --------------------------------------------------
template <int NPART>
__global__ void __launch_bounds__(256)
k_gemm_nt(const float* __restrict__ A, size_t aPartStride,
          const float* __restrict__ abias, int lda, int sAz,
          const float* __restrict__ Bm, int ldb, int sBz,
          float* __restrict__ C, int ldc, int sCz, int K) {
    __shared__ __align__(16) float As2[16][128];
    __shared__ __align__(16) float Bs[16][64];
    size_t aoff = (size_t)blockIdx.z * sAz + (size_t)blockIdx.y * 64 * lda;
    const float* Ar  = A + aoff;
    const float* abr = abias ? abias + (size_t)blockIdx.z * sAz : nullptr;
    const float* Br  = Bm + (size_t)blockIdx.z * sBz + (size_t)blockIdx.x * 64 * ldb;
    float* Cr = C + (size_t)blockIdx.z * sCz + (size_t)blockIdx.y * 64 * ldc
                  + (size_t)blockIdx.x * 64;
    gemm_core<NPART>(Ar, aPartStride, abr, lda, Br, ldb, Cr, ldc, K, As2, Bs);
}

// ----- merged: qproj split-K x4 (blocks 0..255) + row norms (256..1279) --------
__global__ void __launch_bounds__(256)
k_pre_qproj(const float* __restrict__ vis, const float* __restrict__ tmem,
            const float* __restrict__ ipw, float* __restrict__ out_loss) {
    __shared__ __align__(16) float As2[16][128];
    __shared__ __align__(16) float Bs[16][64];
    __shared__ float red[8];
    if (blockIdx.x < 256) {
        int bx = blockIdx.x;
        int kc = bx >> 6, yt = (bx >> 3) & 7, xt = bx & 7;
        const float* A = vis + (size_t)yt * 64 * kD + kc * 128;
        const float* B = ipw + (size_t)xt * 64 * kD + kc * 128;
        float* C = g_qp + (size_t)kc * kB * kD + (size_t)yt * 64 * kD + xt * 64;
        gemm_core<1>(A, 0, nullptr, kD, B, kD, C, kD, 128, As2, Bs);
    } else {
        int idx = blockIdx.x - 256;           // 0..1023
        int t = threadIdx.x;
        if (blockIdx.x == 256 && t == 0) out_loss[0] = 0.f;   // init loss accumulator
        const float* x;
        float* outp;
        if (idx < kB) { x = vis + (size_t)idx * kD;  outp = g_vn + (size_t)idx * kD; }
        else          { x = tmem + (size_t)idx * kD; outp = g_negs + (size_t)idx * kD; }
        float ss = 0.f;
        for (int i = t; i < kD; i += 256) { float v = x[i]; ss += v * v; }
        ss = warp_sum(ss);
        if ((t & 31) == 0) red[t >> 5] = ss;
        __syncthreads();
        float tot = red[0] + red[1] + red[2] + red[3] + red[4] + red[5] + red[6] + red[7];
        float inv = 1.0f / fmaxf(sqrtf(tot), kEps);
        for (int i = t; i < kD; i += 256) outp[i] = x[i] * inv;
    }
}

// ----- qt[b,h,d] = (1/8) * sum_dh (Σ4 q partials + bq)[b,h,dh] * Wk[.,d] -------
__global__ void __launch_bounds__(256)
k_qt_kernel(const float* __restrict__ wk, const float* __restrict__ bq) {
    int h = blockIdx.z, b0 = blockIdx.y * 64, d0 = blockIdx.x * 64;
    __shared__ __align__(16) float Qs2[64][128];   // [dh][2b] dup'd, pre-scaled 1/8
    __shared__ __align__(16) float Ws[64][64];     // [dh][d]
    int tid = threadIdx.x;

    {
        int lr = tid >> 2, lk = (tid & 3) << 2;
        const float* q0 = g_qp + (size_t)(b0 + lr) * kD + h * kDH;
        const float* bqh = bq + h * kDH;
#pragma unroll
        for (int c = 0; c < 4; c++) {
            float4 v = *(const float4*)(bqh + lk + c * 16);
#pragma unroll
            for (int p = 0; p < 4; p++) {
                float4 vp = *(const float4*)(q0 + (size_t)p * kB * kD + lk + c * 16);
                v.x += vp.x; v.y += vp.y; v.z += vp.z; v.w += vp.w;
            }
            int cc = lk + c * 16;
            *(unsigned long long*)&Qs2[cc + 0][2 * lr] = dup2(0.125f * v.x);
            *(unsigned long long*)&Qs2[cc + 1][2 * lr] = dup2(0.125f * v.y);
            *(unsigned long long*)&Qs2[cc + 2][2 * lr] = dup2(0.125f * v.z);
            *(unsigned long long*)&Qs2[cc + 3][2 * lr] = dup2(0.125f * v.w);
        }
    }
    {
        int wr = tid >> 2, wc = (tid & 3) << 2;
        const float* wrow = wk + (size_t)(h * kDH + wr) * kD + d0;
#pragma unroll
        for (int c = 0; c < 4; c++)
            *(float4*)&Ws[wr][wc + c * 16] = *(const float4*)(wrow + wc + c * 16);
    }
    __syncthreads();

    int tx = tid & 15, ty = tid >> 4;
    unsigned long long acc[4][2] = {};
#pragma unroll 8
    for (int k = 0; k < 64; k++) {
        ulonglong2 ap0 = *(const ulonglong2*)&Qs2[k][ty * 8];
        ulonglong2 ap1 = *(const ulonglong2*)&Qs2[k][ty * 8 + 4];
        ulonglong2 bp  = *(const ulonglong2*)&Ws[k][tx * 4];
        fma2(acc[0][0], ap0.x, bp.x); fma2(acc[0][1], ap0.x, bp.y);
        fma2(acc[1][0], ap0.y, bp.x); fma2(acc[1][1], ap0.y, bp.y);
        fma2(acc[2][0], ap1.x, bp.x); fma2(acc[2][1], ap1.x, bp.y);
        fma2(acc[3][0], ap1.y, bp.x); fma2(acc[3][1], ap1.y, bp.y);
    }
#pragma unroll
    for (int i = 0; i < 4; i++) {
        float2 c0 = unpack2(acc[i][0]);
        float2 c1 = unpack2(acc[i][1]);
        *(float4*)&g_qt[(size_t)(b0 + ty * 4 + i) * (kH * kD) + (size_t)h * kD + d0 + tx * 4]
            = make_float4(c0.x, c0.y, c1.x, c1.y);
    }
}

// ----- ctx split-K x4: ctx_p[kc][b, h*64+dh] = tctx[b,h,kc-qtr] @ Wv_h^T -------
__global__ void __launch_bounds__(256)
k_ctx(const float* __restrict__ wv) {
    __shared__ __align__(16) float As2[16][128];
    __shared__ __align__(16) float Bs[16][64];
    int kc = blockIdx.x, b0 = blockIdx.y * 64, h = blockIdx.z;
    const float* A = g_tctx + (size_t)b0 * (kH * kD) + (size_t)h * kD + kc * 128;
    const float* B = wv + (size_t)h * kDH * kD + kc * 128;
    float* C = g_ctxp + (size_t)kc * kB * kD + (size_t)b0 * kD + (size_t)h * kDH;
    gemm_core<1>(A, 0, nullptr, kH * kD, B, kD, C, kD, 128, As2, Bs);
}

// ----- merged: corr split-K x2 (blocks 0..127) + nsims mem-half x2 (128..255) --
__global__ void __launch_bounds__(256)
k_corr_nsims(const float* __restrict__ opw, const float* __restrict__ bv) {
    __shared__ __align__(16) float As2[16][128];
    __shared__ __align__(16) float Bs[16][64];
    if (blockIdx.x < 128) {
        int bx = blockIdx.x;
        int kc = bx >> 6, yt = (bx >> 3) & 7, xt = bx & 7;
        const float* A = g_ctxp + (size_t)yt * 64 * kD + kc * 256;
        const float* B = opw + (size_t)xt * 64 * kD + kc * 256;
        float* C = g_corr + (size_t)kc * kB * kD + (size_t)yt * 64 * kD + xt * 64;
        gemm_core<4>(A, (size_t)kB * kD, bv + kc * 256, kD, B, kD, C, kD, 256, As2, Bs);
    } else {
        int idx = blockIdx.x - 128;            // 0..127, mem-half splitK x2
        int kc = idx >> 6, yt = (idx >> 3) & 7, xt = idx & 7;
        const float* A = g_vn + (size_t)yt * 64 * kD + kc * 256;
        const float* B = g_negs + (size_t)(kB + xt * 64) * kD + kc * 256;
        float* C = g_nsims + (size_t)kc * kB * kNegC + (size_t)yt * 64 * kNegC
                 + kB + xt * 64;
        gemm_core<1>(A, 0, nullptr, kD, B, kD, C, kNegC, 256, As2, Bs);
    }
}

// ----- attention stage 1: sims + sort/cluster + logits + softmax -> g_attn -----
__global__ void __launch_bounds__(256, 2)
k_attn1(const float* __restrict__ text, float* __restrict__ out_cs) {
    __shared__ float sdot[kM], sss[kM];
    __shared__ float sims[128];
    __shared__ __align__(16) float attn2[kM][kH];
    int b = blockIdx.x, t = threadIdx.x;
    int w = t >> 5, lane = t & 31;                  // 8 warps

    const float4* qt4  = (const float4*)(g_qt + (size_t)b * kH * kD);
    const float4* vn4  = (const float4*)(g_vn + (size_t)b * kD);
    const float4* trow = (const float4*)(text + (size_t)b * kM * kD);

#pragma unroll 1
    for (int half = 0; half < 2; half++) {
        float qa[kH][8];
#pragma unroll
        for (int h = 0; h < kH; h++)
#pragma unroll
            for (int j = 0; j < 2; j++) {
                float4 v = qt4[h * 128 + half * 64 + lane + 32 * j];
                qa[h][j * 4 + 0] = v.x; qa[h][j * 4 + 1] = v.y;
                qa[h][j * 4 + 2] = v.z; qa[h][j * 4 + 3] = v.w;
            }
        float vnr[8];
#pragma unroll
        for (int j = 0; j < 2; j++) {
            float4 v = vn4[half * 64 + lane + 32 * j];
            vnr[j * 4 + 0] = v.x; vnr[j * 4 + 1] = v.y;
            vnr[j * 4 + 2] = v.z; vnr[j * 4 + 3] = v.w;
        }

        float4 pre[2];
        {
            const float4* r = trow + (size_t)w * 128 + half * 64;
            pre[0] = r[lane]; pre[1] = r[lane + 32];
        }
        for (int m = w; m < kM; m += 8) {
            float tx[8];
            tx[0] = pre[0].x; tx[1] = pre[0].y; tx[2] = pre[0].z; tx[3] = pre[0].w;
            tx[4] = pre[1].x; tx[5] = pre[1].y; tx[6] = pre[1].z; tx[7] = pre[1].w;
            if (m + 8 < kM) {
                const float4* r = trow + (size_t)(m + 8) * 128 + half * 64;
                pre[0] = r[lane]; pre[1] = r[lane + 32];
            }
            float dot = 0.f, ss = 0.f, a[kH] = {};
#pragma unroll
            for (int i = 0; i < 8; i++) {
                float tv = tx[i];
                dot += vnr[i] * tv; ss += tv * tv;
#pragma unroll
                for (int h = 0; h < kH; h++) a[h] += qa[h][i] * tv;
            }
            dot = warp_sum(dot); ss = warp_sum(ss);
#pragma unroll
            for (int h = 0; h < kH; h++) a[h] = warp_sum(a[h]);
            if (lane == 0) {
                if (half == 0) {
                    sdot[m] = dot; sss[m] = ss;
#pragma unroll
                    for (int h = 0; h < kH; h++) attn2[m][h] = a[h];
                } else {
                    sdot[m] += dot; sss[m] += ss;
#pragma unroll
                    for (int h = 0; h < kH; h++) attn2[m][h] += a[h];
                }
            }
        }
    }
    __syncthreads();

    if (t < kM) sims[t] = sdot[t] / fmaxf(sqrtf(sss[t]), kEps);
    else if (t < 128) sims[t] = -1e30f;
    __syncthreads();

    for (int k = 2; k <= 128; k <<= 1)
        for (int j = k >> 1; j > 0; j >>= 1) {
            if (t < 128) {
                int ixj = t ^ j;
                if (ixj > t) {
                    float a = sims[t], c = sims[ixj];
                    bool up = ((t & k) == 0);
                    if ((a > c) == up) { sims[t] = c; sims[ixj] = a; }
                }
            }
            __syncthreads();
        }

    if (t < kM) {
        float v = sims[127 - t];
        float mean = warp_sum(v) * (1.0f / 32.0f);
        float dv = v - mean;
        float var = warp_sum(dv * dv) * (1.0f / 31.0f);
        if (lane == 0) out_cs[b * kNC + (t >> 5)] = mean / (sqrtf(var) + 1e-6f);
    }

    {
        int h = w;
        float v0 = attn2[lane][h], v1 = attn2[lane + 32][h], v2 = attn2[lane + 64][h];
        float mx = warp_max(fmaxf(v0, fmaxf(v1, v2)));
        v0 = expf(v0 - mx); v1 = expf(v1 - mx); v2 = expf(v2 - mx);
        float inv = 1.0f / warp_sum(v0 + v1 + v2);
        float* ab = g_attn + (size_t)b * kM * kH + h;
        ab[(size_t)lane * kH]        = v0 * inv;
        ab[(size_t)(lane + 32) * kH] = v1 * inv;
        ab[(size_t)(lane + 64) * kH] = v2 * inv;
    }
}

// ----- attention stage 2: tctx[b,h,2t..2t+1] = sum_m attn[b,m,h]*text[b,m,.] ---
__global__ void __launch_bounds__(256)
k_attn2(const float* __restrict__ text) {
    __shared__ __align__(16) float sat[kM * kH];    // 768 floats
    int b = blockIdx.x, t = threadIdx.x;
    {
        const float* ab = g_attn + (size_t)b * kM * kH;
        for (int i = t; i < kM * kH; i += 256) sat[i] = ab[i];
    }
    __syncthreads();

    const float2* tp = (const float2*)(text + (size_t)b * kM * kD) + t;
    float2 acc[kH] = {};
#pragma unroll 8
    for (int m = 0; m < kM; m++) {
        float2 tv = tp[(size_t)m * 256];
        float4 a0 = *(const float4*)&sat[m * kH];
        float4 a1 = *(const float4*)&sat[m * kH + 4];
        acc[0].x += a0.x * tv.x; acc[0].y += a0.x * tv.y;
        acc[1].x += a0.y * tv.x; acc[1].y += a0.y * tv.y;
        acc[2].x += a0.z * tv.x; acc[2].y += a0.z * tv.y;
        acc[3].x += a0.w * tv.x; acc[3].y += a0.w * tv.y;
        acc[4].x += a1.x * tv.x; acc[4].y += a1.x * tv.y;
        acc[5].x += a1.y * tv.x; acc[5].y += a1.y * tv.y;
        acc[6].x += a1.z * tv.x; acc[6].y += a1.z * tv.y;
        acc[7].x += a1.w * tv.x; acc[7].y += a1.w * tv.y;
    }
    float* tb = g_tctx + (size_t)b * kH * kD;
#pragma unroll
    for (int h = 0; h < kH; h++) ((float2*)(tb + h * kD))[t] = acc[h];
}

// ----- combine corr partials + opb, copy to d_out, normalize, pos_sim ---------
__global__ void k_cn_pos(float* __restrict__ out_corr, const float* __restrict__ opb) {
    int b = blockIdx.x, t = threadIdx.x;  // 256
    const float* x0 = g_corr + (size_t)b * kD;
    const float* x1 = g_corr + (size_t)kB * kD + (size_t)b * kD;
    const float* vnb = g_vn + (size_t)b * kD;
    float vals[2];
    float ss = 0.f, dt = 0.f;
#pragma unroll
    for (int j = 0; j < 2; j++) {
        int i = t + j * 256;
        float v = x0[i] + x1[i] + opb[i];
        vals[j] = v;
        out_corr[(size_t)b * kD + i] = v;
        ss += v * v; dt += vnb[i] * v;
    }
    __shared__ float rs[8], rd[8];
    ss = warp_sum(ss); dt = warp_sum(dt);
    if ((t & 31) == 0) { rs[t >> 5] = ss; rd[t >> 5] = dt; }
    __syncthreads();
    float s2 = rs[0] + rs[1] + rs[2] + rs[3] + rs[4] + rs[5] + rs[6] + rs[7];
    float d2 = rd[0] + rd[1] + rd[2] + rd[3] + rd[4] + rd[5] + rd[6] + rd[7];
    float inv = 1.0f / fmaxf(sqrtf(s2), kEps);
    if (t == 0) g_pos[b] = d2 * inv;
#pragma unroll
    for (int j = 0; j < 2; j++)
        g_negs[(size_t)b * kD + t + j * 256] = vals[j] * inv;
}

// ----- warp-per-b top-5 (cn sims count twice) + loss, atomic accumulate --------
// cn columns: 4 partials; mem columns: 2 partials.
__device__ __forceinline__ void ins5(float (&t5)[5], float v) {
    if (v > t5[4]) {
        t5[4] = v;
        if (t5[4] > t5[3]) { float tm = t5[3]; t5[3] = t5[4]; t5[4] = tm; }
        if (t5[3] > t5[2]) { float tm = t5[2]; t5[2] = t5[3]; t5[3] = tm; }
        if (t5[2] > t5[1]) { float tm = t5[1]; t5[1] = t5[2]; t5[2] = tm; }
        if (t5[1] > t5[0]) { float tm = t5[0]; t5[0] = t5[1]; t5[1] = tm; }
    }
}
__global__ void __launch_bounds__(256)
k_loss(const float* __restrict__ tpl, const float* __restrict__ tnl,
       float* __restrict__ out_loss) {
    int b = blockIdx.x * 8 + (threadIdx.x >> 5);
    int lane = threadIdx.x & 31;
    const float* ns0 = g_nsims + (size_t)b * kNegC;
    const size_t ps = (size_t)kB * kNegC;
    float t5[5] = {-1e30f, -1e30f, -1e30f, -1e30f, -1e30f};
    for (int i = lane; i < 512; i += 32) {      // cn sims: 4 partials, multiplicity 2
        float v = ns0[i] + ns0[ps + i] + ns0[2 * ps + i] + ns0[3 * ps + i];
        ins5(t5, v); ins5(t5, v);
    }
    for (int i = 512 + lane; i < 1024; i += 32) // mem sims: 2 partials
        ins5(t5, ns0[i] + ns0[ps + i]);

    float tau_n = expf(tnl[0]);
    int ptr = 0;
    float neg = 0.f;
#pragma unroll
    for (int r = 0; r < 5; r++) {
        float mine = (ptr == 0) ? t5[0] : (ptr == 1) ? t5[1] : (ptr == 2) ? t5[2]
                   : (ptr == 3) ? t5[3] : (ptr == 4) ? t5[4] : -1e30f;
        float mx = warp_max(mine);
        unsigned bal = __ballot_sync(0xffffffffu, mine == mx);
        if (lane == (__ffs(bal) - 1)) ptr++;
        neg += expf(mx / tau_n);
    }
    if (lane == 0) {
        float tau_p = expf(tpl[0]);
        float pos = expf(g_pos[b] / tau_p);
        atomicAdd(out_loss, -logf(pos / (pos + neg + 1e-8f)) * (1.0f / (float)kB));
    }
}

// ---------------------------------------------------------------------------
extern "C" void kernel_launch(void* const* d_in, const int* in_sizes, int n_in,
                              void* d_out, int out_size) {
    const float* vis  = (const float*)d_in[0];
    const float* text = (const float*)d_in[1];
    const float* ipw  = (const float*)d_in[2];
    const float* ipb  = (const float*)d_in[3];
    const float* opw  = (const float*)d_in[4];
    const float* opb  = (const float*)d_in[5];
    const float* tmem = (const float*)d_in[6];
    const float* tpl  = (const float*)d_in[7];
    const float* tnl  = (const float*)d_in[8];

    float* out      = (float*)d_out;
    float* out_corr = out + 1;
    float* out_cs   = out + 1 + kB * kD;

    float *p_vn, *p_negs, *p_nsims;
    cudaGetSymbolAddress((void**)&p_vn,    g_vn);
    cudaGetSymbolAddress((void**)&p_negs,  g_negs);
    cudaGetSymbolAddress((void**)&p_nsims, g_nsims);

    // 1. qproj split-K x4 + vis/mem row norms + loss-accumulator init
    k_pre_qproj<<<256 + 2 * kB, 256>>>(vis, tmem, ipw, out);
    // 2. qt = (1/8)(Σ4 q partials + bq)_h @ Wk_h   (512 blocks)
    k_qt_kernel<<<dim3(kD / 64, kB / 64, kH), 256>>>(ipw + (size_t)kD * kD, ipb);
    // 3. attention stage 1 -> g_attn (512 blocks)
    k_attn1<<<kB, 256>>>(text, out_cs);
    // 4. attention stage 2 -> g_tctx (512 blocks, float2/thread)
    k_attn2<<<kB, 256>>>(text);
    // 5. ctx split-K x4 per head (256 blocks)
    k_ctx<<<dim3(4, kB / 64, kH), 256>>>(ipw + 2 * (size_t)kD * kD);
    // 6. corr split-K x2 (128 blocks) + nsims mem-half x2 (128 blocks)
    k_corr_nsims<<<256, 256>>>(opw, ipb + 2 * kD);
    // 7. combine corr partials + opb -> d_out, normalize into g_negs[0:512], pos
    k_cn_pos<<<kB, 256>>>(out_corr, opb);
    // 8. nsims cn-half split-K x4 (256 blocks, K=128 each)
    k_gemm_nt<1><<<dim3(kB / 64, kB / 64, 4), 256>>>(
        p_vn, 0, nullptr, kD, 128,
        p_negs, kD, 128, p_nsims, kNegC, kB * kNegC, 128);
    // 9. top-5 + per-row loss (4 cn partials, 2 mem partials), atomic mean
    k_loss<<<kB / 8, 256>>>(tpl, tnl, out);
}